// round 13
// baseline (speedup 1.0000x reference)
#include <cuda_runtime.h>
#include <cuda_fp16.h>
#include <cstdint>

// ---------------- problem constants ----------------
#define Dd   1024
#define Hh   16
#define DHd  64
#define Bb   4
#define Nn   1024
#define Ee   (2*Dd + DHd)      // 2112
#define TOK  (Bb*Nn)           // 4096

// ---------------- scratch (device globals; no allocs allowed) ----------------
__device__ __half g_M   [(size_t)Hh*Dd*Dd];      //  32 MB  M' = Wk_h @ Wq_h^T
__device__ __half g_t   [(size_t)Hh*TOK*Dd];     // 128 MB  t = x @ M_h
__device__ __half g_A   [(size_t)Bb*Hh*Nn*Nn];   // 128 MB  scores/probs
__device__ __half g_vT  [(size_t)Hh*128*TOK];    //  16 MB  v^T [h][dh(pad128)][tok]
__device__ __half g_sa  [(size_t)TOK*Dd];        //   8 MB  sa
__device__ __half g_x   [(size_t)TOK*Dd];        //   8 MB  half(x)
__device__ __half g_WpT [(size_t)Dd*Dd];         //   2 MB  Wp^T
__device__ __half g_wvT [(size_t)Hh*128*Dd];     //   4 MB  Wv^T [h][e(pad128)][d]
__device__ float  g_u   [Hh*Dd];
__device__ float  g_w   [Hh*Dd];
__device__ float  g_c   [Hh];
__device__ float  g_rq  [Bb*Hh*Nn];
__device__ float  g_rk  [Bb*Hh*Nn];

// ---------------- helpers ----------------
__device__ __forceinline__ uint32_t smem_u32(const void* p) {
    uint32_t a;
    asm("{ .reg .u64 t; cvta.to.shared.u64 t, %1; cvt.u32.u64 %0, t; }"
        : "=r"(a) : "l"(p));
    return a;
}

__device__ __forceinline__ void mma_f16(float* d, const uint32_t* a, const uint32_t* b) {
    asm volatile(
        "mma.sync.aligned.m16n8k16.row.col.f32.f16.f16.f32 "
        "{%0,%1,%2,%3}, {%4,%5,%6,%7}, {%8,%9}, {%0,%1,%2,%3};\n"
        : "+f"(d[0]), "+f"(d[1]), "+f"(d[2]), "+f"(d[3])
        : "r"(a[0]), "r"(a[1]), "r"(a[2]), "r"(a[3]),
          "r"(b[0]), "r"(b[1]));
}

__device__ __forceinline__ void ldmx4(uint32_t* r, uint32_t addr) {
    asm volatile("ldmatrix.sync.aligned.m8n8.x4.shared.b16 {%0,%1,%2,%3}, [%4];"
                 : "=r"(r[0]), "=r"(r[1]), "=r"(r[2]), "=r"(r[3])
                 : "r"(addr));
}

__device__ __forceinline__ void cpa16(uint32_t dst_smem, const void* src) {
    asm volatile("cp.async.cg.shared.global [%0], [%1], 16;\n"
                 :: "r"(dst_smem), "l"(src));
}
__device__ __forceinline__ void cp_commit() {
    asm volatile("cp.async.commit_group;\n");
}
template<int N>
__device__ __forceinline__ void cp_wait() {
    asm volatile("cp.async.wait_group %0;\n" :: "n"(N));
}

__device__ __forceinline__ uint32_t h2u(__half2 h) {
    return *reinterpret_cast<uint32_t*>(&h);
}

// ---------------- fp16 batched GEMM (m16n8k16, cp.async 3-stage, ldmatrix) -----
// C[z][m][n] = sum_k A[m,k] * B[n,k]  (+ bias[n])   [k-contiguous operands]
// AF32=1: A,B are fp32 in gmem (strides in floats), converted to fp16 inline.
struct GemmP {
    const __half* A; const __half* B; void* C; const float* bias;
    int as_m, bs_row, cs_m;
    long long a_so, a_si, b_so, b_si, c_so, c_si, bias_so;
    int M, N, K, zdiv;
    int causal;   // skip CTAs fully above the diagonal
    int klimit;   // K_eff = min(K, m0+128)
    int ct;       // store C transposed (half only)
    int cf32;     // C is float (else half)
};

#define BM 128
#define BK 64
#define ROWB 144                       // smem row stride bytes (64 halves + 8 pad)
#define A_TILE_B (BM*ROWB)             // 18432
#define STAGES 3

template<int BN, int AF32>
__global__ __launch_bounds__(256, 2) void gemm_f16_kernel(GemmP p) {
    constexpr int B_TILE_B = BN * ROWB;
    constexpr int STAGE_B  = A_TILE_B + B_TILE_B;
    constexpr int NT = BN / 32;        // n-tiles of 8 per warp (warp n-extent = BN/4)
    constexpr int PP = (NT + 1) / 2;   // b-ldmatrix.x4 per k16 step

    extern __shared__ char smem[];

    if (p.causal && ((int)blockIdx.x > (int)blockIdx.y)) return;

    const int z  = blockIdx.z;
    const long long zo = z / p.zdiv;
    const long long zi = z % p.zdiv;

    const void* AbV;
    const void* BvV;
    if (AF32) {
        AbV = (const void*)((const float*)p.A + zo * p.a_so + zi * p.a_si);
        BvV = (const void*)((const float*)p.B + zo * p.b_so + zi * p.b_si);
    } else {
        AbV = (const void*)(p.A + zo * p.a_so + zi * p.a_si);
        BvV = (const void*)(p.B + zo * p.b_so + zi * p.b_si);
    }

    const int m0 = blockIdx.y * BM;
    const int n0 = blockIdx.x * BN;
    const int nColsB = min(BN, p.N - n0);

    const int tid  = threadIdx.x;
    const int warp = tid >> 5;
    const int lane = tid & 31;
    const int wm   = (warp >> 2) * 64;        // warp grid 2 x 4 over 128 x BN
    const int wn   = (warp & 3) * (BN / 4);
    const int grp  = lane >> 2;
    const int t4   = lane & 3;

    const int K_eff = p.klimit ? min(p.K, m0 + BM) : p.K;
    const int nIter = K_eff / BK;

    const uint32_t sbase = smem_u32(smem);

    auto load_tiles = [&](int st, int k0) {
        if (AF32) {
            const float* Af = (const float*)AbV;
            const float* Bf = (const float*)BvV;
#pragma unroll
            for (int i = 0; i < 4; i++) {
                int ch = tid + i * 256;
                int row = ch >> 3, c = ch & 7;
                const float* s = Af + (size_t)(m0 + row) * p.as_m + k0 + c * 8;
                float4 v0 = __ldg((const float4*)s);
                float4 v1 = __ldg((const float4*)(s + 4));
                uint4 w;
                w.x = h2u(__floats2half2_rn(v0.x, v0.y));
                w.y = h2u(__floats2half2_rn(v0.z, v0.w));
                w.z = h2u(__floats2half2_rn(v1.x, v1.y));
                w.w = h2u(__floats2half2_rn(v1.z, v1.w));
                *reinterpret_cast<uint4*>(smem + st * STAGE_B + row * ROWB + c * 16) = w;
            }
#pragma unroll
            for (int i = 0; i < BN / 32; i++) {
                int ch = tid + i * 256;
                int row = ch >> 3, c = ch & 7;
                if (row < nColsB) {
                    const float* s = Bf + (size_t)(n0 + row) * p.bs_row + k0 + c * 8;
                    float4 v0 = __ldg((const float4*)s);
                    float4 v1 = __ldg((const float4*)(s + 4));
                    uint4 w;
                    w.x = h2u(__floats2half2_rn(v0.x, v0.y));
                    w.y = h2u(__floats2half2_rn(v0.z, v0.w));
                    w.z = h2u(__floats2half2_rn(v1.x, v1.y));
                    w.w = h2u(__floats2half2_rn(v1.z, v1.w));
                    *reinterpret_cast<uint4*>(smem + st * STAGE_B + A_TILE_B +
                                              row * ROWB + c * 16) = w;
                }
            }
        } else {
            const __half* Ab = (const __half*)AbV;
            const __half* Bv = (const __half*)BvV;
            const uint32_t abase = sbase + st * STAGE_B;
#pragma unroll
            for (int i = 0; i < 4; i++) {
                int ch = tid + i * 256;
                int row = ch >> 3, c = ch & 7;
                cpa16(abase + row * ROWB + c * 16,
                      Ab + (size_t)(m0 + row) * p.as_m + k0 + c * 8);
            }
            const uint32_t bbase = abase + A_TILE_B;
#pragma unroll
            for (int i = 0; i < BN / 32; i++) {
                int ch = tid + i * 256;
                int row = ch >> 3, c = ch & 7;
                if (row < nColsB)
                    cpa16(bbase + row * ROWB + c * 16,
                          Bv + (size_t)(n0 + row) * p.bs_row + k0 + c * 8);
            }
            cp_commit();
        }
    };

    // ldmatrix lane addressing (byte offsets within stage)
    const uint32_t la_off = (uint32_t)((wm + (lane & 15)) * ROWB + (lane >> 4) * 16);
    const uint32_t lb_off = (uint32_t)(A_TILE_B +
                     (wn + (lane & 7) + ((lane >> 4) << 3)) * ROWB +
                     ((lane >> 3) & 1) * 16);

    float acc[4][NT][4];
#pragma unroll
    for (int i = 0; i < 4; i++)
#pragma unroll
        for (int j = 0; j < NT; j++)
#pragma unroll
            for (int r = 0; r < 4; r++) acc[i][j][r] = 0.f;

    load_tiles(0, 0);
    load_tiles(1, BK);

    // single-sync mainloop: [wait(it) -> sync -> compute(it) -> load(it+2)]
    for (int it = 0; it < nIter; it++) {
        if (!AF32) {
            if (it + 1 < nIter) cp_wait<1>();
            else                cp_wait<0>();
        }
        __syncthreads();

        const int st = it % STAGES;
        const uint32_t aBase = sbase + st * STAGE_B + la_off;
        const uint32_t bBase = sbase + st * STAGE_B + lb_off;

#pragma unroll
        for (int ks = 0; ks < 4; ks++) {      // 4 x k16 = BK
            uint32_t a[4][4];
            uint32_t breg[PP][4];
#pragma unroll
            for (int mt = 0; mt < 4; mt++)
                ldmx4(a[mt], aBase + mt * (16 * ROWB) + ks * 32);
#pragma unroll
            for (int pp = 0; pp < PP; pp++)
                ldmx4(breg[pp], bBase + pp * (16 * ROWB) + ks * 32);
#pragma unroll
            for (int mt = 0; mt < 4; mt++)
#pragma unroll
                for (int nt = 0; nt < NT; nt++)
                    mma_f16(acc[mt][nt], a[mt], &breg[nt >> 1][(nt & 1) * 2]);
        }

        if (it + 2 < nIter) load_tiles((it + 2) % STAGES, (it + 2) * BK);
    }

    const float* biasb = p.bias ? (p.bias + zo * p.bias_so) : nullptr;

    if (p.cf32) {
        float* Cb = (float*)p.C + zo * p.c_so + zi * p.c_si;
#pragma unroll
        for (int mt = 0; mt < 4; mt++) {
#pragma unroll
            for (int nt = 0; nt < NT; nt++) {
                int c = n0 + wn + nt * 8 + t4 * 2;
                if (c >= p.N) continue;
                float b0 = 0.f, b1 = 0.f;
                if (biasb) { b0 = biasb[c]; b1 = biasb[c + 1]; }
#pragma unroll
                for (int rr = 0; rr < 2; rr++) {
                    int row = m0 + wm + mt * 16 + grp + rr * 8;
                    float2 v2;
                    v2.x = acc[mt][nt][rr * 2]     + b0;
                    v2.y = acc[mt][nt][rr * 2 + 1] + b1;
                    *reinterpret_cast<float2*>(Cb + (size_t)row * p.cs_m + c) = v2;
                }
            }
        }
    } else {
        __half* Cb = (__half*)p.C + zo * p.c_so + zi * p.c_si;
#pragma unroll
        for (int mt = 0; mt < 4; mt++) {
#pragma unroll
            for (int nt = 0; nt < NT; nt++) {
                int c = n0 + wn + nt * 8 + t4 * 2;
                if (c >= p.N) continue;
                float b0 = 0.f, b1 = 0.f;
                if (biasb) { b0 = biasb[c]; b1 = biasb[c + 1]; }
#pragma unroll
                for (int rr = 0; rr < 2; rr++) {
                    int row = m0 + wm + mt * 16 + grp + rr * 8;
                    float v0 = acc[mt][nt][rr * 2]     + b0;
                    float v1 = acc[mt][nt][rr * 2 + 1] + b1;
                    if (!p.ct) {
                        *reinterpret_cast<__half2*>(Cb + (size_t)row * p.cs_m + c) =
                            __floats2half2_rn(v0, v1);
                    } else {
                        Cb[(size_t)c       * p.cs_m + row] = __float2half_rn(v0);
                        Cb[(size_t)(c + 1) * p.cs_m + row] = __float2half_rn(v1);
                    }
                }
            }
        }
    }
}

#define SMEM_BYTES_128 (STAGES * (A_TILE_B + 128 * ROWB))   // 110592
#define SMEM_BYTES_64  (STAGES * (A_TILE_B + 64 * ROWB))    //  82944

// ---------------- prepass kernels ----------------
__global__ void f2h_kernel(const float4* __restrict__ src, __half2* __restrict__ dst, int n4) {
    int i = blockIdx.x * blockDim.x + threadIdx.x;
    if (i < n4) {
        float4 v = src[i];
        dst[2 * i]     = __floats2half2_rn(v.x, v.y);
        dst[2 * i + 1] = __floats2half2_rn(v.z, v.w);
    }
}

// dst[c*drs + r] = half(src[r*srs + c]) ; per-z batch offsets
__global__ void transpose_h_kernel(const float* __restrict__ src, __half* __restrict__ dst,
                                   int R, int C, int srs, int drs,
                                   long long s_bs, long long d_bs) {
    __shared__ float tile[32][33];
    src += (long long)blockIdx.z * s_bs;
    dst += (long long)blockIdx.z * d_bs;
    int r0 = blockIdx.y * 32, c0 = blockIdx.x * 32;
    int tx = threadIdx.x, ty = threadIdx.y;  // 32 x 8
#pragma unroll
    for (int i = 0; i < 32; i += 8) {
        int r = r0 + ty + i, c = c0 + tx;
        if (r < R && c < C) tile[ty + i][tx] = src[(size_t)r * srs + c];
    }
    __syncthreads();
#pragma unroll
    for (int i = 0; i < 32; i += 8) {
        int c = c0 + ty + i, r = r0 + tx;
        if (r < R && c < C) dst[(size_t)c * drs + r] = __float2half_rn(tile[tx][ty + i]);
    }
}

// ---------------- bias-correction prep kernels (exact, fp32 inputs) ----------------
__global__ void prep_uw_kernel(const float* __restrict__ Wkqv, const float* __restrict__ bkqv,
                               float* __restrict__ u, float* __restrict__ w) {
    int gw = (blockIdx.x * blockDim.x + threadIdx.x) >> 5;
    if (gw >= Hh * Dd) return;
    int lane = threadIdx.x & 31;
    int h = gw >> 10;
    int i = gw & (Dd - 1);
    const float* row = Wkqv + ((long long)h * Dd + i) * Ee;
    const float* bh  = bkqv + (long long)h * Ee;
    float s1 = 0.f, s2 = 0.f;
    for (int e = lane; e < Dd; e += 32) {
        s1 += row[Dd + e] * bh[e];
        s2 += row[e]      * bh[Dd + e];
    }
#pragma unroll
    for (int o = 16; o > 0; o >>= 1) {
        s1 += __shfl_xor_sync(0xffffffffu, s1, o);
        s2 += __shfl_xor_sync(0xffffffffu, s2, o);
    }
    if (lane == 0) { u[gw] = s1; w[gw] = s2; }
}

__global__ void prep_c_kernel(const float* __restrict__ bkqv, float* __restrict__ c) {
    int h = threadIdx.x >> 5;
    if (h >= Hh) return;
    int lane = threadIdx.x & 31;
    const float* bh = bkqv + (long long)h * Ee;
    float s = 0.f;
    for (int e = lane; e < Dd; e += 32) s += bh[Dd + e] * bh[e];
#pragma unroll
    for (int o = 16; o > 0; o >>= 1) s += __shfl_xor_sync(0xffffffffu, s, o);
    if (lane == 0) c[h] = s;
}

__global__ void prep_rqrk_kernel(const float* __restrict__ x, const float* __restrict__ u,
                                 const float* __restrict__ w, float* __restrict__ rq,
                                 float* __restrict__ rk) {
    int gw = (blockIdx.x * blockDim.x + threadIdx.x) >> 5;
    if (gw >= TOK * Hh) return;
    int lane = threadIdx.x & 31;
    int h   = gw & (Hh - 1);
    int tok = gw >> 4;
    const float* xr = x + (long long)tok * Dd;
    const float* uh = u + h * Dd;
    const float* wh = w + h * Dd;
    float s1 = 0.f, s2 = 0.f;
    for (int i = lane; i < Dd; i += 32) {
        float xv = xr[i];
        s1 += xv * uh[i];
        s2 += xv * wh[i];
    }
#pragma unroll
    for (int o = 16; o > 0; o >>= 1) {
        s1 += __shfl_xor_sync(0xffffffffu, s1, o);
        s2 += __shfl_xor_sync(0xffffffffu, s2, o);
    }
    if (lane == 0) {
        int b = tok >> 10, n = tok & (Nn - 1);
        int z = b * Hh + h;
        rq[z * Nn + n] = s1;
        rk[z * Nn + n] = s2;
    }
}

// ---- causal softmax: A = softmax((raw + rq_n + rk_m + c_h)/32), I/O-minimized ----
__global__ void softmax_kernel(__half* __restrict__ A, const float* __restrict__ rq,
                               const float* __restrict__ rk, const float* __restrict__ cvec) {
    const int row = blockIdx.x;
    const int z = row >> 10;
    const int n = row & (Nn - 1);
    const int h = z & (Hh - 1);
    __half* rp = A + (long long)z * Nn * Nn + (long long)n * Nn;
    const float* rkz = rk + z * Nn;
    const float addn = rq[z * Nn + n] + cvec[h];
    const int tid = threadIdx.x;
    const int limit = ((n >> 7) + 1) << 7;

    float l[4];
    float mx = -1e30f;
#pragma unroll
    for (int i = 0; i < 4; i++) {
        int m = tid + i * 256;
        float v = -1e30f;
        if (m <= n) v = (__half2float(rp[m]) + addn + rkz[m]) * 0.03125f;
        l[i] = v;
        mx = fmaxf(mx, v);
    }
    __shared__ float red[256];
    red[tid] = mx; __syncthreads();
#pragma unroll
    for (int s = 128; s > 0; s >>= 1) {
        if (tid < s) red[tid] = fmaxf(red[tid], red[tid + s]);
        __syncthreads();
    }
    mx = red[0]; __syncthreads();

    float sum = 0.f;
#pragma unroll
    for (int i = 0; i < 4; i++) {
        float e = (l[i] > -1e29f) ? __expf(l[i] - mx) : 0.f;
        l[i] = e;
        sum += e;
    }
    red[tid] = sum; __syncthreads();
#pragma unroll
    for (int s = 128; s > 0; s >>= 1) {
        if (tid < s) red[tid] += red[tid + s];
        __syncthreads();
    }
    const float inv = 1.f / red[0];
#pragma unroll
    for (int i = 0; i < 4; i++) {
        int m = tid + i * 256;
        if (m < limit) rp[m] = __float2half_rn(l[i] * inv);
    }
}

// ---------------- launch ----------------
extern "C" void kernel_launch(void* const* d_in, const int* in_sizes, int n_in,
                              void* d_out, int out_size) {
    const float* x    = (const float*)d_in[0];
    const float* Wkqv = (const float*)d_in[1];
    const float* bkqv = (const float*)d_in[2];
    const float* Wp   = (const float*)d_in[3];
    const float* bp   = (const float*)d_in[4];
    float* out = (float*)d_out;

    __half *gM, *gt, *gA, *gvT, *gsa, *gx, *gWpT, *gwvT;
    float *gu, *gw, *gc, *grq, *grk;
    cudaGetSymbolAddress((void**)&gM,   g_M);
    cudaGetSymbolAddress((void**)&gt,   g_t);
    cudaGetSymbolAddress((void**)&gA,   g_A);
    cudaGetSymbolAddress((void**)&gvT,  g_vT);
    cudaGetSymbolAddress((void**)&gsa,  g_sa);
    cudaGetSymbolAddress((void**)&gx,   g_x);
    cudaGetSymbolAddress((void**)&gWpT, g_WpT);
    cudaGetSymbolAddress((void**)&gwvT, g_wvT);
    cudaGetSymbolAddress((void**)&gu,   g_u);
    cudaGetSymbolAddress((void**)&gw,   g_w);
    cudaGetSymbolAddress((void**)&gc,   g_c);
    cudaGetSymbolAddress((void**)&grq,  g_rq);
    cudaGetSymbolAddress((void**)&grk,  g_rk);

    // one-time resource setup (runs on the uncaptured correctness call)
    static int inited = 0;
    static cudaStream_t s2;
    static cudaEvent_t evFork, evX, evJoin, evK3a, evHalfA;
    if (!inited) {
        cudaFuncSetAttribute((void*)gemm_f16_kernel<128, 0>,
                             cudaFuncAttributeMaxDynamicSharedMemorySize, SMEM_BYTES_128);
        cudaFuncSetAttribute((void*)gemm_f16_kernel<128, 1>,
                             cudaFuncAttributeMaxDynamicSharedMemorySize, SMEM_BYTES_128);
        cudaFuncSetAttribute((void*)gemm_f16_kernel<64, 0>,
                             cudaFuncAttributeMaxDynamicSharedMemorySize, SMEM_BYTES_64);
        cudaStreamCreateWithFlags(&s2, cudaStreamNonBlocking);
        cudaEventCreateWithFlags(&evFork,  cudaEventDisableTiming);
        cudaEventCreateWithFlags(&evX,     cudaEventDisableTiming);
        cudaEventCreateWithFlags(&evJoin,  cudaEventDisableTiming);
        cudaEventCreateWithFlags(&evK3a,   cudaEventDisableTiming);
        cudaEventCreateWithFlags(&evHalfA, cudaEventDisableTiming);
        inited = 1;
    }

    // ---- fork track 2 immediately ----
    cudaEventRecord(evFork, 0);
    cudaStreamWaitEvent(s2, evFork, 0);

    // track 2: f2h(x), transposes, preps, K4
    {
        int n4 = TOK * Dd / 4;
        f2h_kernel<<<(n4 + 255) / 256, 256, 0, s2>>>((const float4*)x, (__half2*)gx, n4);
    }
    cudaEventRecord(evX, s2);
    transpose_h_kernel<<<dim3(32, 32, 1), dim3(32, 8), 0, s2>>>(
        Wp, gWpT, Dd, Dd, Dd, Dd, 0, 0);
    transpose_h_kernel<<<dim3(2, 32, Hh), dim3(32, 8), 0, s2>>>(
        Wkqv + 2 * Dd, gwvT, Dd, DHd, Ee, Dd,
        (long long)Dd * Ee, (long long)128 * Dd);
    prep_uw_kernel<<<(Hh * Dd * 32 + 255) / 256, 256, 0, s2>>>(Wkqv, bkqv, gu, gw);
    prep_c_kernel<<<1, 512, 0, s2>>>(bkqv, gc);
    prep_rqrk_kernel<<<(TOK * Hh * 32 + 255) / 256, 256, 0, s2>>>(x, gu, gw, grq, grk);
    // K4: v^T_h = (X @ Wv_h + bv)^T
    {
        GemmP p{};
        p.A = gx; p.as_m = Dd; p.a_so = 0; p.a_si = 0;
        p.B = gwvT; p.bs_row = Dd; p.b_so = (long long)128 * Dd; p.b_si = 0;
        p.C = gvT; p.cs_m = TOK; p.c_so = (long long)128 * TOK; p.c_si = 0;
        p.bias = bkqv + 2 * Dd; p.bias_so = Ee;
        p.M = TOK; p.N = DHd; p.K = Dd; p.zdiv = 1;
        p.causal = 0; p.klimit = 0; p.ct = 1; p.cf32 = 0;
        gemm_f16_kernel<64, 0><<<dim3(1, 32, Hh), 256, SMEM_BYTES_64, s2>>>(p);
    }
    cudaEventRecord(evJoin, s2);

    // ---- main stream: K1 reads fp32 Wkqv directly (no f2h needed) ----
    // K1: M'_h = Wk_h @ Wq_h^T   per head 1024x1024x1024
    {
        GemmP p{};
        p.A = (const __half*)Wkqv;        p.as_m = Ee;   // fp32 strides (floats)
        p.a_so = (long long)Dd * Ee; p.a_si = 0;
        p.B = (const __half*)(Wkqv + Dd); p.bs_row = Ee;
        p.b_so = (long long)Dd * Ee; p.b_si = 0;
        p.C = gM; p.cs_m = Dd; p.c_so = (long long)Dd * Dd; p.c_si = 0;
        p.bias = nullptr; p.bias_so = 0;
        p.M = Dd; p.N = Dd; p.K = Dd; p.zdiv = 1;
        p.causal = 0; p.klimit = 0; p.ct = 0; p.cf32 = 0;
        gemm_f16_kernel<128, 1><<<dim3(8, 8, Hh), 256, SMEM_BYTES_128>>>(p);
    }
    // K2 needs gx from track 2
    cudaStreamWaitEvent(0, evX, 0);
    // K2: t_h = X @ M_h   per head 4096x1024x1024
    {
        GemmP p{};
        p.A = gx; p.as_m = Dd; p.a_so = 0; p.a_si = 0;
        p.B = gM; p.bs_row = Dd; p.b_so = (long long)Dd * Dd; p.b_si = 0;
        p.C = gt; p.cs_m = Dd; p.c_so = (long long)TOK * Dd; p.c_si = 0;
        p.bias = nullptr; p.bias_so = 0;
        p.M = TOK; p.N = Dd; p.K = Dd; p.zdiv = 1;
        p.causal = 0; p.klimit = 0; p.ct = 0; p.cf32 = 0;
        gemm_f16_kernel<128, 0><<<dim3(8, 32, Hh), 256, SMEM_BYTES_128>>>(p);
    }
    // K3a: batches b=0,1 (z 0..31)
    {
        GemmP p{};
        p.A = gt; p.as_m = Dd;
        p.a_so = (long long)Nn * Dd;
        p.a_si = (long long)TOK * Dd;
        p.B = gx; p.bs_row = Dd;
        p.b_so = (long long)Nn * Dd; p.b_si = 0;
        p.C = gA; p.cs_m = Nn;
        p.c_so = (long long)Hh * Nn * Nn; p.c_si = (long long)Nn * Nn;
        p.bias = nullptr; p.bias_so = 0;
        p.M = Nn; p.N = Nn; p.K = Dd; p.zdiv = Hh;
        p.causal = 1; p.klimit = 0; p.ct = 0; p.cf32 = 0;
        gemm_f16_kernel<128, 0><<<dim3(8, 8, 2 * Hh), 256, SMEM_BYTES_128>>>(p);
    }
    cudaEventRecord(evK3a, 0);

    // s2: softmax_a + K5a overlapped with K3b (s2 already holds track-2 deps)
    cudaStreamWaitEvent(s2, evK3a, 0);
    softmax_kernel<<<2 * Hh * Nn, 256, 0, s2>>>(gA, grq, grk, gc);
    {
        GemmP p{};
        p.A = gA; p.as_m = Nn;
        p.a_so = (long long)Hh * Nn * Nn; p.a_si = (long long)Nn * Nn;
        p.B = gvT; p.bs_row = TOK;
        p.b_so = Nn;
        p.b_si = (long long)128 * TOK;
        p.C = gsa; p.cs_m = Dd;
        p.c_so = (long long)Nn * Dd;
        p.c_si = DHd;
        p.bias = nullptr; p.bias_so = 0;
        p.M = Nn; p.N = DHd; p.K = Nn; p.zdiv = Hh;
        p.causal = 0; p.klimit = 1; p.ct = 0; p.cf32 = 0;
        gemm_f16_kernel<64, 0><<<dim3(1, 8, 2 * Hh), 256, SMEM_BYTES_64, s2>>>(p);
    }
    cudaEventRecord(evHalfA, s2);

    // main: K3b (b=2,3)
    {
        GemmP p{};
        p.A = gt + (long long)2 * Nn * Dd; p.as_m = Dd;
        p.a_so = (long long)Nn * Dd;
        p.a_si = (long long)TOK * Dd;
        p.B = gx + (long long)2 * Nn * Dd; p.bs_row = Dd;
        p.b_so = (long long)Nn * Dd; p.b_si = 0;
        p.C = gA + (long long)2 * Hh * Nn * Nn; p.cs_m = Nn;
        p.c_so = (long long)Hh * Nn * Nn; p.c_si = (long long)Nn * Nn;
        p.bias = nullptr; p.bias_so = 0;
        p.M = Nn; p.N = Nn; p.K = Dd; p.zdiv = Hh;
        p.causal = 1; p.klimit = 0; p.ct = 0; p.cf32 = 0;
        gemm_f16_kernel<128, 0><<<dim3(8, 8, 2 * Hh), 256, SMEM_BYTES_128>>>(p);
    }

    // main needs rq/rk/c (+ gvT for K5b) from track 2
    cudaStreamWaitEvent(0, evJoin, 0);
    softmax_kernel<<<2 * Hh * Nn, 256>>>(gA + (long long)2 * Hh * Nn * Nn,
                                         grq + 2 * Hh * Nn, grk + 2 * Hh * Nn, gc);
    {
        GemmP p{};
        p.A = gA + (long long)2 * Hh * Nn * Nn; p.as_m = Nn;
        p.a_so = (long long)Hh * Nn * Nn; p.a_si = (long long)Nn * Nn;
        p.B = gvT + (long long)2 * Nn; p.bs_row = TOK;
        p.b_so = Nn;
        p.b_si = (long long)128 * TOK;
        p.C = gsa + (long long)2 * Nn * Dd; p.cs_m = Dd;
        p.c_so = (long long)Nn * Dd;
        p.c_si = DHd;
        p.bias = nullptr; p.bias_so = 0;
        p.M = Nn; p.N = DHd; p.K = Nn; p.zdiv = Hh;
        p.causal = 0; p.klimit = 1; p.ct = 0; p.cf32 = 0;
        gemm_f16_kernel<64, 0><<<dim3(1, 8, 2 * Hh), 256, SMEM_BYTES_64>>>(p);
    }

    // K6 needs sa from both halves
    cudaStreamWaitEvent(0, evHalfA, 0);
    // K6: out = sa @ Wp + bp   4096x1024x1024  (fp32 output)
    {
        GemmP p{};
        p.A = gsa; p.as_m = Dd; p.a_so = 0; p.a_si = 0;
        p.B = gWpT; p.bs_row = Dd; p.b_so = 0; p.b_si = 0;
        p.C = out; p.cs_m = Dd; p.c_so = 0; p.c_si = 0;
        p.bias = bp; p.bias_so = 0;
        p.M = TOK; p.N = Dd; p.K = Dd; p.zdiv = 1;
        p.causal = 0; p.klimit = 0; p.ct = 0; p.cf32 = 1;
        gemm_f16_kernel<128, 0><<<dim3(8, 32, 1), 256, SMEM_BYTES_128>>>(p);
    }
}

// round 14
// speedup vs baseline: 1.0570x; 1.0570x over previous
#include <cuda_runtime.h>
#include <cuda_fp16.h>
#include <cstdint>

// ---------------- problem constants ----------------
#define Dd   1024
#define Hh   16
#define DHd  64
#define Bb   4
#define Nn   1024
#define Ee   (2*Dd + DHd)      // 2112
#define TOK  (Bb*Nn)           // 4096

// ---------------- scratch (device globals; no allocs allowed) ----------------
__device__ __half g_M   [(size_t)Hh*Dd*Dd];      //  32 MB  M' = Wk_h @ Wq_h^T
__device__ __half g_t   [(size_t)Hh*TOK*Dd];     // 128 MB  t = x @ M_h
__device__ __half g_A   [(size_t)Bb*Hh*Nn*Nn];   // 128 MB  scores/probs
__device__ __half g_vT  [(size_t)Hh*128*TOK];    //  16 MB  v^T [h][dh(pad128)][tok]
__device__ __half g_sa  [(size_t)TOK*Dd];        //   8 MB  sa
__device__ __half g_x   [(size_t)TOK*Dd];        //   8 MB  half(x)
__device__ __half g_wkqv[(size_t)Hh*Dd*Ee];      //  69 MB  half(Wkqv)
__device__ __half g_WpT [(size_t)Dd*Dd];         //   2 MB  Wp^T
__device__ __half g_wvT [(size_t)Hh*128*Dd];     //   4 MB  Wv^T [h][e(pad128)][d]
__device__ float  g_u   [Hh*Dd];
__device__ float  g_w   [Hh*Dd];
__device__ float  g_c   [Hh];
__device__ float  g_rq  [Bb*Hh*Nn];
__device__ float  g_rk  [Bb*Hh*Nn];

// ---------------- helpers ----------------
__device__ __forceinline__ uint32_t smem_u32(const void* p) {
    uint32_t a;
    asm("{ .reg .u64 t; cvta.to.shared.u64 t, %1; cvt.u32.u64 %0, t; }"
        : "=r"(a) : "l"(p));
    return a;
}

__device__ __forceinline__ void mma_f16(float* d, const uint32_t* a, const uint32_t* b) {
    asm volatile(
        "mma.sync.aligned.m16n8k16.row.col.f32.f16.f16.f32 "
        "{%0,%1,%2,%3}, {%4,%5,%6,%7}, {%8,%9}, {%0,%1,%2,%3};\n"
        : "+f"(d[0]), "+f"(d[1]), "+f"(d[2]), "+f"(d[3])
        : "r"(a[0]), "r"(a[1]), "r"(a[2]), "r"(a[3]),
          "r"(b[0]), "r"(b[1]));
}

__device__ __forceinline__ void ldmx4(uint32_t* r, uint32_t addr) {
    asm volatile("ldmatrix.sync.aligned.m8n8.x4.shared.b16 {%0,%1,%2,%3}, [%4];"
                 : "=r"(r[0]), "=r"(r[1]), "=r"(r[2]), "=r"(r[3])
                 : "r"(addr));
}

__device__ __forceinline__ void cpa16(uint32_t dst_smem, const void* src) {
    asm volatile("cp.async.cg.shared.global [%0], [%1], 16;\n"
                 :: "r"(dst_smem), "l"(src));
}
__device__ __forceinline__ void cp_commit() {
    asm volatile("cp.async.commit_group;\n");
}
template<int N>
__device__ __forceinline__ void cp_wait() {
    asm volatile("cp.async.wait_group %0;\n" :: "n"(N));
}

// ---------------- fp16 batched GEMM (m16n8k16, cp.async 3-stage, ldmatrix) -----
// C[z][m][n] = sum_k A[m,k] * B[n,k]  (+ bias[n])   [A,B half, k-contiguous]
struct GemmP {
    const __half* A; const __half* B; void* C; const float* bias;
    int as_m, bs_row, cs_m;
    long long a_so, a_si, b_so, b_si, c_so, c_si, bias_so;
    int M, N, K, zdiv;
    int causal;   // skip CTAs fully above the diagonal
    int klimit;   // K_eff = min(K, m0+128)
    int ct;       // store C transposed (half only)
    int cf32;     // C is float (else half)
};

#define BM 128
#define BK 64
#define ROWB 144                       // smem row stride bytes (64 halves + 8 pad)
#define A_TILE_B (BM*ROWB)             // 18432
#define STAGES 3

// BN = 128 (full) or 64 (narrow, for N=64 GEMMs — no wasted MMA columns)
template<int BN>
__global__ __launch_bounds__(256, 2) void gemm_f16_kernel(GemmP p) {
    constexpr int B_TILE_B = BN * ROWB;
    constexpr int STAGE_B  = A_TILE_B + B_TILE_B;
    constexpr int NT = BN / 32;        // n-tiles of 8 per warp (warp n-extent = BN/4)
    constexpr int PP = (NT + 1) / 2;   // b-ldmatrix.x4 per k16 step

    extern __shared__ char smem[];

    if (p.causal && ((int)blockIdx.x > (int)blockIdx.y)) return;

    const int z  = blockIdx.z;
    const long long zo = z / p.zdiv;
    const long long zi = z % p.zdiv;

    const __half* Ab = p.A + zo * p.a_so + zi * p.a_si;
    const __half* Bv = p.B + zo * p.b_so + zi * p.b_si;

    const int m0 = blockIdx.y * BM;
    const int n0 = blockIdx.x * BN;
    const int nColsB = min(BN, p.N - n0);

    const int tid  = threadIdx.x;
    const int warp = tid >> 5;
    const int lane = tid & 31;
    const int wm   = (warp >> 2) * 64;        // warp grid 2 x 4 over 128 x BN
    const int wn   = (warp & 3) * (BN / 4);
    const int grp  = lane >> 2;
    const int t4   = lane & 3;

    const int K_eff = p.klimit ? min(p.K, m0 + BM) : p.K;
    const int nIter = K_eff / BK;

    const uint32_t sbase = smem_u32(smem);

    auto load_tiles = [&](int st, int k0) {
        const uint32_t abase = sbase + st * STAGE_B;
#pragma unroll
        for (int i = 0; i < 4; i++) {
            int ch = tid + i * 256;
            int row = ch >> 3, c = ch & 7;
            cpa16(abase + row * ROWB + c * 16,
                  Ab + (size_t)(m0 + row) * p.as_m + k0 + c * 8);
        }
        const uint32_t bbase = abase + A_TILE_B;
#pragma unroll
        for (int i = 0; i < BN / 32; i++) {
            int ch = tid + i * 256;
            int row = ch >> 3, c = ch & 7;
            if (row < nColsB)
                cpa16(bbase + row * ROWB + c * 16,
                      Bv + (size_t)(n0 + row) * p.bs_row + k0 + c * 8);
        }
        cp_commit();
    };

    // ldmatrix lane addressing (byte offsets within stage)
    const uint32_t la_off = (uint32_t)((wm + (lane & 15)) * ROWB + (lane >> 4) * 16);
    const uint32_t lb_off = (uint32_t)(A_TILE_B +
                     (wn + (lane & 7) + ((lane >> 4) << 3)) * ROWB +
                     ((lane >> 3) & 1) * 16);

    float acc[4][NT][4];
#pragma unroll
    for (int i = 0; i < 4; i++)
#pragma unroll
        for (int j = 0; j < NT; j++)
#pragma unroll
            for (int r = 0; r < 4; r++) acc[i][j][r] = 0.f;

    load_tiles(0, 0);
    load_tiles(1, BK);

    // single-sync mainloop: [wait(it) -> sync -> compute(it) -> load(it+2)]
    // WAR-safe: load at end of iter it writes stage (it+2)%3 == (it-1)%3, whose
    // readers (compute of iter it-1) all passed the sync at top of iter it.
    for (int it = 0; it < nIter; it++) {
        if (it + 1 < nIter) cp_wait<1>();
        else                cp_wait<0>();
        __syncthreads();

        const int st = it % STAGES;
        const uint32_t aBase = sbase + st * STAGE_B + la_off;
        const uint32_t bBase = sbase + st * STAGE_B + lb_off;

#pragma unroll
        for (int ks = 0; ks < 4; ks++) {      // 4 x k16 = BK
            uint32_t a[4][4];
            uint32_t breg[PP][4];
#pragma unroll
            for (int mt = 0; mt < 4; mt++)
                ldmx4(a[mt], aBase + mt * (16 * ROWB) + ks * 32);
#pragma unroll
            for (int pp = 0; pp < PP; pp++)
                ldmx4(breg[pp], bBase + pp * (16 * ROWB) + ks * 32);
#pragma unroll
            for (int mt = 0; mt < 4; mt++)
#pragma unroll
                for (int nt = 0; nt < NT; nt++)
                    mma_f16(acc[mt][nt], a[mt], &breg[nt >> 1][(nt & 1) * 2]);
        }

        if (it + 2 < nIter) load_tiles((it + 2) % STAGES, (it + 2) * BK);
    }

    const float* biasb = p.bias ? (p.bias + zo * p.bias_so) : nullptr;

    if (p.cf32) {
        float* Cb = (float*)p.C + zo * p.c_so + zi * p.c_si;
#pragma unroll
        for (int mt = 0; mt < 4; mt++) {
#pragma unroll
            for (int nt = 0; nt < NT; nt++) {
                int c = n0 + wn + nt * 8 + t4 * 2;
                if (c >= p.N) continue;
                float b0 = 0.f, b1 = 0.f;
                if (biasb) { b0 = biasb[c]; b1 = biasb[c + 1]; }
#pragma unroll
                for (int rr = 0; rr < 2; rr++) {
                    int row = m0 + wm + mt * 16 + grp + rr * 8;
                    float2 v2;
                    v2.x = acc[mt][nt][rr * 2]     + b0;
                    v2.y = acc[mt][nt][rr * 2 + 1] + b1;
                    *reinterpret_cast<float2*>(Cb + (size_t)row * p.cs_m + c) = v2;
                }
            }
        }
    } else {
        __half* Cb = (__half*)p.C + zo * p.c_so + zi * p.c_si;
#pragma unroll
        for (int mt = 0; mt < 4; mt++) {
#pragma unroll
            for (int nt = 0; nt < NT; nt++) {
                int c = n0 + wn + nt * 8 + t4 * 2;
                if (c >= p.N) continue;
                float b0 = 0.f, b1 = 0.f;
                if (biasb) { b0 = biasb[c]; b1 = biasb[c + 1]; }
#pragma unroll
                for (int rr = 0; rr < 2; rr++) {
                    int row = m0 + wm + mt * 16 + grp + rr * 8;
                    float v0 = acc[mt][nt][rr * 2]     + b0;
                    float v1 = acc[mt][nt][rr * 2 + 1] + b1;
                    if (!p.ct) {
                        *reinterpret_cast<__half2*>(Cb + (size_t)row * p.cs_m + c) =
                            __floats2half2_rn(v0, v1);
                    } else {
                        Cb[(size_t)c       * p.cs_m + row] = __float2half_rn(v0);
                        Cb[(size_t)(c + 1) * p.cs_m + row] = __float2half_rn(v1);
                    }
                }
            }
        }
    }
}

#define SMEM_BYTES_128 (STAGES * (A_TILE_B + 128 * ROWB))   // 110592
#define SMEM_BYTES_64  (STAGES * (A_TILE_B + 64 * ROWB))    //  82944

// ---------------- prepass kernels ----------------
__global__ void f2h_kernel(const float4* __restrict__ src, __half2* __restrict__ dst, int n4) {
    int i = blockIdx.x * blockDim.x + threadIdx.x;
    if (i < n4) {
        float4 v = src[i];
        dst[2 * i]     = __floats2half2_rn(v.x, v.y);
        dst[2 * i + 1] = __floats2half2_rn(v.z, v.w);
    }
}

// dst[c*drs + r] = half(src[r*srs + c]) ; per-z batch offsets
__global__ void transpose_h_kernel(const float* __restrict__ src, __half* __restrict__ dst,
                                   int R, int C, int srs, int drs,
                                   long long s_bs, long long d_bs) {
    __shared__ float tile[32][33];
    src += (long long)blockIdx.z * s_bs;
    dst += (long long)blockIdx.z * d_bs;
    int r0 = blockIdx.y * 32, c0 = blockIdx.x * 32;
    int tx = threadIdx.x, ty = threadIdx.y;  // 32 x 8
#pragma unroll
    for (int i = 0; i < 32; i += 8) {
        int r = r0 + ty + i, c = c0 + tx;
        if (r < R && c < C) tile[ty + i][tx] = src[(size_t)r * srs + c];
    }
    __syncthreads();
#pragma unroll
    for (int i = 0; i < 32; i += 8) {
        int c = c0 + ty + i, r = r0 + tx;
        if (r < R && c < C) dst[(size_t)c * drs + r] = __float2half_rn(tile[tx][ty + i]);
    }
}

// ---------------- bias-correction prep kernels (exact, fp32 inputs) ----------------
__global__ void prep_uw_kernel(const float* __restrict__ Wkqv, const float* __restrict__ bkqv,
                               float* __restrict__ u, float* __restrict__ w) {
    int gw = (blockIdx.x * blockDim.x + threadIdx.x) >> 5;
    if (gw >= Hh * Dd) return;
    int lane = threadIdx.x & 31;
    int h = gw >> 10;
    int i = gw & (Dd - 1);
    const float* row = Wkqv + ((long long)h * Dd + i) * Ee;
    const float* bh  = bkqv + (long long)h * Ee;
    float s1 = 0.f, s2 = 0.f;
    for (int e = lane; e < Dd; e += 32) {
        s1 += row[Dd + e] * bh[e];
        s2 += row[e]      * bh[Dd + e];
    }
#pragma unroll
    for (int o = 16; o > 0; o >>= 1) {
        s1 += __shfl_xor_sync(0xffffffffu, s1, o);
        s2 += __shfl_xor_sync(0xffffffffu, s2, o);
    }
    if (lane == 0) { u[gw] = s1; w[gw] = s2; }
}

__global__ void prep_c_kernel(const float* __restrict__ bkqv, float* __restrict__ c) {
    int h = threadIdx.x >> 5;
    if (h >= Hh) return;
    int lane = threadIdx.x & 31;
    const float* bh = bkqv + (long long)h * Ee;
    float s = 0.f;
    for (int e = lane; e < Dd; e += 32) s += bh[Dd + e] * bh[e];
#pragma unroll
    for (int o = 16; o > 0; o >>= 1) s += __shfl_xor_sync(0xffffffffu, s, o);
    if (lane == 0) c[h] = s;
}

__global__ void prep_rqrk_kernel(const float* __restrict__ x, const float* __restrict__ u,
                                 const float* __restrict__ w, float* __restrict__ rq,
                                 float* __restrict__ rk) {
    int gw = (blockIdx.x * blockDim.x + threadIdx.x) >> 5;
    if (gw >= TOK * Hh) return;
    int lane = threadIdx.x & 31;
    int h   = gw & (Hh - 1);
    int tok = gw >> 4;
    const float* xr = x + (long long)tok * Dd;
    const float* uh = u + h * Dd;
    const float* wh = w + h * Dd;
    float s1 = 0.f, s2 = 0.f;
    for (int i = lane; i < Dd; i += 32) {
        float xv = xr[i];
        s1 += xv * uh[i];
        s2 += xv * wh[i];
    }
#pragma unroll
    for (int o = 16; o > 0; o >>= 1) {
        s1 += __shfl_xor_sync(0xffffffffu, s1, o);
        s2 += __shfl_xor_sync(0xffffffffu, s2, o);
    }
    if (lane == 0) {
        int b = tok >> 10, n = tok & (Nn - 1);
        int z = b * Hh + h;
        rq[z * Nn + n] = s1;
        rk[z * Nn + n] = s2;
    }
}

// ---- causal softmax: A = softmax((raw + rq_n + rk_m + c_h)/32), I/O-minimized ----
__global__ void softmax_kernel(__half* __restrict__ A, const float* __restrict__ rq,
                               const float* __restrict__ rk, const float* __restrict__ cvec) {
    const int row = blockIdx.x;
    const int z = row >> 10;
    const int n = row & (Nn - 1);
    const int h = z & (Hh - 1);
    __half* rp = A + (long long)z * Nn * Nn + (long long)n * Nn;
    const float* rkz = rk + z * Nn;
    const float addn = rq[z * Nn + n] + cvec[h];
    const int tid = threadIdx.x;
    const int limit = ((n >> 7) + 1) << 7;

    float l[4];
    float mx = -1e30f;
#pragma unroll
    for (int i = 0; i < 4; i++) {
        int m = tid + i * 256;
        float v = -1e30f;
        if (m <= n) v = (__half2float(rp[m]) + addn + rkz[m]) * 0.03125f;
        l[i] = v;
        mx = fmaxf(mx, v);
    }
    __shared__ float red[256];
    red[tid] = mx; __syncthreads();
#pragma unroll
    for (int s = 128; s > 0; s >>= 1) {
        if (tid < s) red[tid] = fmaxf(red[tid], red[tid + s]);
        __syncthreads();
    }
    mx = red[0]; __syncthreads();

    float sum = 0.f;
#pragma unroll
    for (int i = 0; i < 4; i++) {
        float e = (l[i] > -1e29f) ? __expf(l[i] - mx) : 0.f;
        l[i] = e;
        sum += e;
    }
    red[tid] = sum; __syncthreads();
#pragma unroll
    for (int s = 128; s > 0; s >>= 1) {
        if (tid < s) red[tid] += red[tid + s];
        __syncthreads();
    }
    const float inv = 1.f / red[0];
#pragma unroll
    for (int i = 0; i < 4; i++) {
        int m = tid + i * 256;
        if (m < limit) rp[m] = __float2half_rn(l[i] * inv);
    }
}

// ---------------- launch ----------------
extern "C" void kernel_launch(void* const* d_in, const int* in_sizes, int n_in,
                              void* d_out, int out_size) {
    const float* x    = (const float*)d_in[0];
    const float* Wkqv = (const float*)d_in[1];
    const float* bkqv = (const float*)d_in[2];
    const float* Wp   = (const float*)d_in[3];
    const float* bp   = (const float*)d_in[4];
    float* out = (float*)d_out;

    __half *gM, *gt, *gA, *gvT, *gsa, *gx, *gwk, *gWpT, *gwvT;
    float *gu, *gw, *gc, *grq, *grk;
    cudaGetSymbolAddress((void**)&gM,   g_M);
    cudaGetSymbolAddress((void**)&gt,   g_t);
    cudaGetSymbolAddress((void**)&gA,   g_A);
    cudaGetSymbolAddress((void**)&gvT,  g_vT);
    cudaGetSymbolAddress((void**)&gsa,  g_sa);
    cudaGetSymbolAddress((void**)&gx,   g_x);
    cudaGetSymbolAddress((void**)&gwk,  g_wkqv);
    cudaGetSymbolAddress((void**)&gWpT, g_WpT);
    cudaGetSymbolAddress((void**)&gwvT, g_wvT);
    cudaGetSymbolAddress((void**)&gu,   g_u);
    cudaGetSymbolAddress((void**)&gw,   g_w);
    cudaGetSymbolAddress((void**)&gc,   g_c);
    cudaGetSymbolAddress((void**)&grq,  g_rq);
    cudaGetSymbolAddress((void**)&grk,  g_rk);

    // one-time resource setup (runs on the uncaptured correctness call)
    static int inited = 0;
    static cudaStream_t s2;
    static cudaEvent_t evFork, evX, evJoin, evK3a, evHalfA;
    if (!inited) {
        cudaFuncSetAttribute(gemm_f16_kernel<128>,
                             cudaFuncAttributeMaxDynamicSharedMemorySize, SMEM_BYTES_128);
        cudaFuncSetAttribute(gemm_f16_kernel<64>,
                             cudaFuncAttributeMaxDynamicSharedMemorySize, SMEM_BYTES_64);
        cudaStreamCreateWithFlags(&s2, cudaStreamNonBlocking);
        cudaEventCreateWithFlags(&evFork,  cudaEventDisableTiming);
        cudaEventCreateWithFlags(&evX,     cudaEventDisableTiming);
        cudaEventCreateWithFlags(&evJoin,  cudaEventDisableTiming);
        cudaEventCreateWithFlags(&evK3a,   cudaEventDisableTiming);
        cudaEventCreateWithFlags(&evHalfA, cudaEventDisableTiming);
        inited = 1;
    }

    // ---- fork track 2 immediately (reads only raw inputs at first) ----
    cudaEventRecord(evFork, 0);
    cudaStreamWaitEvent(s2, evFork, 0);

    // track 2: f2h(x), transposes, preps, K4
    {
        int n4 = TOK * Dd / 4;
        f2h_kernel<<<(n4 + 255) / 256, 256, 0, s2>>>((const float4*)x, (__half2*)gx, n4);
    }
    cudaEventRecord(evX, s2);
    transpose_h_kernel<<<dim3(32, 32, 1), dim3(32, 8), 0, s2>>>(
        Wp, gWpT, Dd, Dd, Dd, Dd, 0, 0);
    transpose_h_kernel<<<dim3(2, 32, Hh), dim3(32, 8), 0, s2>>>(
        Wkqv + 2 * Dd, gwvT, Dd, DHd, Ee, Dd,
        (long long)Dd * Ee, (long long)128 * Dd);
    prep_uw_kernel<<<(Hh * Dd * 32 + 255) / 256, 256, 0, s2>>>(Wkqv, bkqv, gu, gw);
    prep_c_kernel<<<1, 512, 0, s2>>>(bkqv, gc);
    prep_rqrk_kernel<<<(TOK * Hh * 32 + 255) / 256, 256, 0, s2>>>(x, gu, gw, grq, grk);
    // K4: v^T_h = (X @ Wv_h + bv)^T
    {
        GemmP p{};
        p.A = gx; p.as_m = Dd; p.a_so = 0; p.a_si = 0;
        p.B = gwvT; p.bs_row = Dd; p.b_so = (long long)128 * Dd; p.b_si = 0;
        p.C = gvT; p.cs_m = TOK; p.c_so = (long long)128 * TOK; p.c_si = 0;
        p.bias = bkqv + 2 * Dd; p.bias_so = Ee;
        p.M = TOK; p.N = DHd; p.K = Dd; p.zdiv = 1;
        p.causal = 0; p.klimit = 0; p.ct = 1; p.cf32 = 0;
        gemm_f16_kernel<64><<<dim3(1, 32, Hh), 256, SMEM_BYTES_64, s2>>>(p);
    }
    cudaEventRecord(evJoin, s2);

    // ---- main stream: heavy chain (round-12 proven config) ----
    {
        int n4 = Hh * Dd * Ee / 4;
        f2h_kernel<<<(n4 + 255) / 256, 256>>>((const float4*)Wkqv, (__half2*)gwk, n4);
    }
    // K1: M'_h = Wk_h @ Wq_h^T   per head 1024x1024x1024
    {
        GemmP p{};
        p.A = gwk;      p.as_m = Ee;   p.a_so = (long long)Dd * Ee; p.a_si = 0;
        p.B = gwk + Dd; p.bs_row = Ee; p.b_so = (long long)Dd * Ee; p.b_si = 0;
        p.C = gM; p.cs_m = Dd; p.c_so = (long long)Dd * Dd; p.c_si = 0;
        p.bias = nullptr; p.bias_so = 0;
        p.M = Dd; p.N = Dd; p.K = Dd; p.zdiv = 1;
        p.causal = 0; p.klimit = 0; p.ct = 0; p.cf32 = 0;
        gemm_f16_kernel<128><<<dim3(8, 8, Hh), 256, SMEM_BYTES_128>>>(p);
    }
    // K2 needs gx from track 2
    cudaStreamWaitEvent(0, evX, 0);
    // K2: t_h = X @ M_h   per head 4096x1024x1024
    {
        GemmP p{};
        p.A = gx; p.as_m = Dd; p.a_so = 0; p.a_si = 0;
        p.B = gM; p.bs_row = Dd; p.b_so = (long long)Dd * Dd; p.b_si = 0;
        p.C = gt; p.cs_m = Dd; p.c_so = (long long)TOK * Dd; p.c_si = 0;
        p.bias = nullptr; p.bias_so = 0;
        p.M = TOK; p.N = Dd; p.K = Dd; p.zdiv = 1;
        p.causal = 0; p.klimit = 0; p.ct = 0; p.cf32 = 0;
        gemm_f16_kernel<128><<<dim3(8, 32, Hh), 256, SMEM_BYTES_128>>>(p);
    }
    // K3a: batches b=0,1 (z 0..31)
    {
        GemmP p{};
        p.A = gt; p.as_m = Dd;
        p.a_so = (long long)Nn * Dd;
        p.a_si = (long long)TOK * Dd;
        p.B = gx; p.bs_row = Dd;
        p.b_so = (long long)Nn * Dd; p.b_si = 0;
        p.C = gA; p.cs_m = Nn;
        p.c_so = (long long)Hh * Nn * Nn; p.c_si = (long long)Nn * Nn;
        p.bias = nullptr; p.bias_so = 0;
        p.M = Nn; p.N = Nn; p.K = Dd; p.zdiv = Hh;
        p.causal = 1; p.klimit = 0; p.ct = 0; p.cf32 = 0;
        gemm_f16_kernel<128><<<dim3(8, 8, 2 * Hh), 256, SMEM_BYTES_128>>>(p);
    }
    cudaEventRecord(evK3a, 0);

    // s2: softmax_a + K5a overlapped with K3b (s2 already ordered after track-2 deps)
    cudaStreamWaitEvent(s2, evK3a, 0);
    softmax_kernel<<<2 * Hh * Nn, 256, 0, s2>>>(gA, grq, grk, gc);
    {
        GemmP p{};
        p.A = gA; p.as_m = Nn;
        p.a_so = (long long)Hh * Nn * Nn; p.a_si = (long long)Nn * Nn;
        p.B = gvT; p.bs_row = TOK;
        p.b_so = Nn;
        p.b_si = (long long)128 * TOK;
        p.C = gsa; p.cs_m = Dd;
        p.c_so = (long long)Nn * Dd;
        p.c_si = DHd;
        p.bias = nullptr; p.bias_so = 0;
        p.M = Nn; p.N = DHd; p.K = Nn; p.zdiv = Hh;
        p.causal = 0; p.klimit = 1; p.ct = 0; p.cf32 = 0;
        gemm_f16_kernel<64><<<dim3(1, 8, 2 * Hh), 256, SMEM_BYTES_64, s2>>>(p);
    }
    cudaEventRecord(evHalfA, s2);

    // main: K3b (b=2,3)
    {
        GemmP p{};
        p.A = gt + (long long)2 * Nn * Dd; p.as_m = Dd;
        p.a_so = (long long)Nn * Dd;
        p.a_si = (long long)TOK * Dd;
        p.B = gx + (long long)2 * Nn * Dd; p.bs_row = Dd;
        p.b_so = (long long)Nn * Dd; p.b_si = 0;
        p.C = gA + (long long)2 * Hh * Nn * Nn; p.cs_m = Nn;
        p.c_so = (long long)Hh * Nn * Nn; p.c_si = (long long)Nn * Nn;
        p.bias = nullptr; p.bias_so = 0;
        p.M = Nn; p.N = Nn; p.K = Dd; p.zdiv = Hh;
        p.causal = 1; p.klimit = 0; p.ct = 0; p.cf32 = 0;
        gemm_f16_kernel<128><<<dim3(8, 8, 2 * Hh), 256, SMEM_BYTES_128>>>(p);
    }

    // main needs rq/rk/c (+ gvT for K5b) from track 2
    cudaStreamWaitEvent(0, evJoin, 0);
    softmax_kernel<<<2 * Hh * Nn, 256>>>(gA + (long long)2 * Hh * Nn * Nn,
                                         grq + 2 * Hh * Nn, grk + 2 * Hh * Nn, gc);
    {
        GemmP p{};
        p.A = gA + (long long)2 * Hh * Nn * Nn; p.as_m = Nn;
        p.a_so = (long long)Hh * Nn * Nn; p.a_si = (long long)Nn * Nn;
        p.B = gvT + (long long)2 * Nn; p.bs_row = TOK;
        p.b_so = Nn;
        p.b_si = (long long)128 * TOK;
        p.C = gsa + (long long)2 * Nn * Dd; p.cs_m = Dd;
        p.c_so = (long long)Nn * Dd;
        p.c_si = DHd;
        p.bias = nullptr; p.bias_so = 0;
        p.M = Nn; p.N = DHd; p.K = Nn; p.zdiv = Hh;
        p.causal = 0; p.klimit = 1; p.ct = 0; p.cf32 = 0;
        gemm_f16_kernel<64><<<dim3(1, 8, 2 * Hh), 256, SMEM_BYTES_64>>>(p);
    }

    // K6 needs sa from both halves
    cudaStreamWaitEvent(0, evHalfA, 0);
    // K6: out = sa @ Wp + bp   4096x1024x1024  (fp32 output)
    {
        GemmP p{};
        p.A = gsa; p.as_m = Dd; p.a_so = 0; p.a_si = 0;
        p.B = gWpT; p.bs_row = Dd; p.b_so = 0; p.b_si = 0;
        p.C = out; p.cs_m = Dd; p.c_so = 0; p.c_si = 0;
        p.bias = bp; p.bias_so = 0;
        p.M = TOK; p.N = Dd; p.K = Dd; p.zdiv = 1;
        p.causal = 0; p.klimit = 0; p.ct = 0; p.cf32 = 1;
        gemm_f16_kernel<128><<<dim3(8, 32, 1), 256, SMEM_BYTES_128>>>(p);
    }
}